// round 15
// baseline (speedup 1.0000x reference)
#include <cuda_runtime.h>
#include <cuda_fp16.h>
#include <cstdint>

// Problem dims
#define NB   4
#define NS   2048
#define ND   1024
#define NH   16
#define NDH  64
#define NBH  (NB * NH)     // 64
#define NM   (NB * NS)     // 8192 tokens
#define N_QKV (3 * ND)     // 3072
#define LOG2E 1.4426950408889634f

// Scratch (static __device__ arrays: allocation-free per harness rules)
// g_C layout: [m][n'] with n' = t*1024 + h*64 + dh  (t: 0=q,1=k,2=v)
__device__ __align__(16) __half g_C[(size_t)NM * N_QKV];
__device__ __half g_ctx[(size_t)NM * ND];          // [b][s][d]
__device__ __half g_Ah[(size_t)NM * ND];           // query, fp16
__device__ __half g_Wt_qkv[(size_t)N_QKV * ND];    // permuted W_qkv^T [3072][1024]
__device__ __half g_Wt_out[(size_t)ND * ND];       // W_out^T [1024][1024]
__device__ float  g_bq[N_QKV];                     // permuted (+Q-scaled) bias

// ---------------------------------------------------------------------------
// helpers
// ---------------------------------------------------------------------------
__device__ __forceinline__ uint32_t smem_u32(const void* p) {
    uint32_t a;
    asm("{ .reg .u64 t; cvta.to.shared.u64 t, %1; cvt.u32.u64 %0, t; }"
        : "=r"(a) : "l"(p));
    return a;
}
__device__ __forceinline__ void cp16(uint32_t dst, const void* src) {
    asm volatile("cp.async.cg.shared.global [%0], [%1], 16;"
                 :: "r"(dst), "l"(src) : "memory");
}
__device__ __forceinline__ void cp_commit() {
    asm volatile("cp.async.commit_group;" ::: "memory");
}
template <int N>
__device__ __forceinline__ void cp_wait() {
    asm volatile("cp.async.wait_group %0;" :: "n"(N) : "memory");
}

// fp16 m16n8k16 mma, fp32 accumulate
__device__ __forceinline__ void mma16(float* c,
                                      unsigned a0, unsigned a1, unsigned a2, unsigned a3,
                                      unsigned b0, unsigned b1) {
    asm volatile(
        "mma.sync.aligned.m16n8k16.row.col.f32.f16.f16.f32 "
        "{%0,%1,%2,%3},{%4,%5,%6,%7},{%8,%9},{%0,%1,%2,%3};"
        : "+f"(c[0]), "+f"(c[1]), "+f"(c[2]), "+f"(c[3])
        : "r"(a0), "r"(a1), "r"(a2), "r"(a3), "r"(b0), "r"(b1));
}

__device__ __forceinline__ void ldm4(unsigned& r0, unsigned& r1, unsigned& r2,
                                     unsigned& r3, uint32_t addr) {
    asm volatile("ldmatrix.sync.aligned.m8n8.x4.shared.b16 {%0,%1,%2,%3}, [%4];"
                 : "=r"(r0), "=r"(r1), "=r"(r2), "=r"(r3) : "r"(addr));
}
__device__ __forceinline__ void ldm4t(unsigned& r0, unsigned& r1, unsigned& r2,
                                      unsigned& r3, uint32_t addr) {
    asm volatile("ldmatrix.sync.aligned.m8n8.x4.trans.shared.b16 {%0,%1,%2,%3}, [%4];"
                 : "=r"(r0), "=r"(r1), "=r"(r2), "=r"(r3) : "r"(addr));
}

// pack two fp32 -> half2 {lo=a, hi=b}
__device__ __forceinline__ unsigned pack_h2(float lo, float hi) {
    unsigned d;
    asm("cvt.rn.f16x2.f32 %0, %1, %2;" : "=r"(d) : "f"(hi), "f"(lo));
    return d;
}
// 2^x for both halves of a half2
__device__ __forceinline__ unsigned ex2_h2(unsigned x) {
    unsigned d;
    asm("ex2.approx.f16x2 %0, %1;" : "=r"(d) : "r"(x));
    return d;
}

// ---------------------------------------------------------------------------
// Prepass: fp32 -> fp16 (4 elements/thread)
// ---------------------------------------------------------------------------
__global__ __launch_bounds__(256) void round_h_kernel(
    const float* __restrict__ src, __half* __restrict__ dst)
{
    size_t i = ((size_t)blockIdx.x * 256 + threadIdx.x) * 4;
    float4 v = *(const float4*)(src + i);
    *(__half2*)(dst + i)     = __floats2half2_rn(v.x, v.y);
    *(__half2*)(dst + i + 2) = __floats2half2_rn(v.z, v.w);
}

// ---------------------------------------------------------------------------
// Transpose + fp16 convert:  dst[C][R] = h(src[R][C])   (W_out path)
// ---------------------------------------------------------------------------
__global__ __launch_bounds__(256) void transpose_h_kernel(
    const float* __restrict__ src, __half* __restrict__ dst, int R, int C)
{
    __shared__ float t[32][33];
    int bx = blockIdx.x * 32;
    int by = blockIdx.y * 32;
    int tx = threadIdx.x & 31, ty = threadIdx.x >> 5;
    #pragma unroll
    for (int j = 0; j < 4; j++)
        t[ty + j * 8][tx] = src[(size_t)(by + ty + j * 8) * C + bx + tx];
    __syncthreads();
    #pragma unroll
    for (int j = 0; j < 4; j++)
        dst[(size_t)(bx + ty + j * 8) * R + by + tx] =
            __float2half_rn(t[tx][ty + j * 8]);
}

// ---------------------------------------------------------------------------
// Permuted transpose of W_qkv:  dst[n'][k] = h(W[k][n] * s),
// n' = t*1024 + h*64 + dh,  n = h*192 + dh*3 + t,  s = (t==0 ? 0.125 : 1).
// ---------------------------------------------------------------------------
__global__ __launch_bounds__(256) void transpose_perm_qkv_kernel(
    const float* __restrict__ W, __half* __restrict__ dst)
{
    __shared__ float t[32][33];
    int npb = blockIdx.x * 32;
    int kb  = blockIdx.y * 32;
    int tx = threadIdx.x & 31, ty = threadIdx.x >> 5;

    int tt  = npb >> 10;
    int rem = npb & 1023;
    int h   = rem >> 6;
    int dh0 = rem & 63;
    int nbase = h * 192 + dh0 * 3 + tt;
    float scale = (tt == 0) ? 0.125f : 1.0f;

    #pragma unroll
    for (int j = 0; j < 4; j++)
        t[tx][ty + j * 8] = W[(size_t)(kb + ty + j * 8) * N_QKV + nbase + tx * 3];
    __syncthreads();
    #pragma unroll
    for (int j = 0; j < 4; j++)
        dst[(size_t)(npb + ty + j * 8) * ND + kb + tx] =
            __float2half_rn(t[ty + j * 8][tx] * scale);
}

// permuted (+Q-scaled) bias: g_bq[n'] = b[n] * s
__global__ __launch_bounds__(256) void bias_perm_kernel(const float* __restrict__ b)
{
    int np = blockIdx.x * 256 + threadIdx.x;     // 0..3071
    int tt = np >> 10;
    int rem = np & 1023;
    int h = rem >> 6, dh = rem & 63;
    int n = h * 192 + dh * 3 + tt;
    g_bq[np] = b[n] * ((tt == 0) ? 0.125f : 1.0f);
}

// ---------------------------------------------------------------------------
// fp16 mma GEMM (round-10 mainloop — best measured; byte-identical).
// Block tile 128x128, BK=64, 3-stage cp.async pipeline, ONE sync/stage,
// 8 warps in 2x4, warp tile 64x32.  110.6KB smem -> 2 CTAs/SM.
// MODE 0: coalesced half2 C(+bias) stores to g_C (permuted layout).
// MODE 1: fp32 out = acc + bias.
// ---------------------------------------------------------------------------
#define GS    72                          // smem row stride (halfs)
#define GT    (128 * GS)                  // halfs per tile (9216)
#define GSTG  (2 * GT)                    // halfs per stage A+B (18432)
#define GEMM_SMEM (3 * GSTG * 2)          // 110592 bytes
#define NSTAGE_K 16                       // K=1024 / BK=64

template <int MODE>
__global__ __launch_bounds__(256, 2) void mm_gemm_kernel(
    const __half* __restrict__ A,
    const __half* __restrict__ Bt,
    const float* __restrict__ bias,
    float* __restrict__ outp)
{
    extern __shared__ __half hsm[];
    uint32_t sb = smem_u32(hsm);

    int tid  = threadIdx.x;
    int warp = tid >> 5, lane = tid & 31;
    int wm   = warp >> 2, wn = warp & 3;      // 2 x 4 warp grid, tile 64x32
    int g    = lane >> 2, tg = lane & 3;
    int m0   = blockIdx.y * 128;
    int n0   = blockIdx.x * 128;

    int lrow = lane & 15;
    int lcol = (lane >> 4) * 8;

    float acc[4][4][4];
    #pragma unroll
    for (int i = 0; i < 4; i++)
        #pragma unroll
        for (int j = 0; j < 4; j++)
            #pragma unroll
            for (int e = 0; e < 4; e++) acc[i][j][e] = 0.f;

    auto prefetch = [&](int t) {
        int st = t % 3;
        int k0 = t * 64;
        uint32_t abase = sb + (uint32_t)(st * GSTG) * 2u;
        uint32_t bbase = abase + (uint32_t)GT * 2u;
        #pragma unroll
        for (int i = 0; i < 4; i++) {
            int ch  = tid + i * 256;              // 0..1023
            int row = ch >> 3, q = ch & 7;
            uint32_t doff = (uint32_t)(row * GS + q * 8) * 2u;
            cp16(abase + doff, A  + (size_t)(m0 + row) * 1024 + k0 + q * 8);
            cp16(bbase + doff, Bt + (size_t)(n0 + row) * 1024 + k0 + q * 8);
        }
        cp_commit();
    };

    prefetch(0);
    prefetch(1);

    for (int s = 0; s < NSTAGE_K; s++) {
        if (s < NSTAGE_K - 1) cp_wait<1>(); else cp_wait<0>();
        __syncthreads();
        if (s + 2 < NSTAGE_K) prefetch(s + 2);

        uint32_t Ab = sb + (uint32_t)((s % 3) * GSTG) * 2u;
        uint32_t Bb = Ab + (uint32_t)GT * 2u;
        #pragma unroll
        for (int kk = 0; kk < 4; kk++) {
            int kb = kk * 16;
            unsigned af[4][4], bf[4][2];
            #pragma unroll
            for (int i = 0; i < 4; i++) {
                uint32_t addr = Ab + (uint32_t)((wm * 64 + i * 16 + lrow) * GS + kb + lcol) * 2u;
                ldm4(af[i][0], af[i][1], af[i][2], af[i][3], addr);
            }
            #pragma unroll
            for (int nt = 0; nt < 2; nt++) {
                unsigned r0, r1, r2, r3;
                uint32_t addr = Bb + (uint32_t)((wn * 32 + nt * 16 + lrow) * GS + kb + lcol) * 2u;
                ldm4(r0, r1, r2, r3, addr);
                bf[nt * 2][0] = r0;  bf[nt * 2 + 1][0] = r1;
                bf[nt * 2][1] = r2;  bf[nt * 2 + 1][1] = r3;
            }
            #pragma unroll
            for (int i = 0; i < 4; i++)
                #pragma unroll
                for (int j = 0; j < 4; j++)
                    mma16(acc[i][j], af[i][0], af[i][1], af[i][2], af[i][3],
                          bf[j][0], bf[j][1]);
        }
    }

    if (MODE == 0) {
        #pragma unroll
        for (int i = 0; i < 4; i++)
            #pragma unroll
            for (int half = 0; half < 2; half++) {
                int m = m0 + wm * 64 + i * 16 + g + half * 8;
                #pragma unroll
                for (int j = 0; j < 4; j++) {
                    int n = n0 + wn * 32 + j * 8 + 2 * tg;
                    __half2 hv = __floats2half2_rn(
                        acc[i][j][half * 2 + 0] + bias[n],
                        acc[i][j][half * 2 + 1] + bias[n + 1]);
                    *(__half2*)(g_C + (size_t)m * N_QKV + n) = hv;
                }
            }
    } else {
        #pragma unroll
        for (int i = 0; i < 4; i++)
            #pragma unroll
            for (int half = 0; half < 2; half++) {
                int m = m0 + wm * 64 + i * 16 + g + half * 8;
                #pragma unroll
                for (int j = 0; j < 4; j++) {
                    int n = n0 + wn * 32 + j * 8 + 2 * tg;
                    float2 v = make_float2(acc[i][j][half * 2 + 0] + bias[n],
                                           acc[i][j][half * 2 + 1] + bias[n + 1]);
                    *(float2*)(outp + (size_t)m * ND + n) = v;
                }
            }
    }
}

// ---------------------------------------------------------------------------
// Causal flash attention — 128-row q tiles, 8 warps (warp w: rows 16w..16w+15).
// Per-warp math byte-identical to round 14; KV loop covers 2qt+2 64-row tiles.
// The extra fully-masked tile for first-half rows contributes exactly zero
// (mask -1e4 -> fp16 ex2 underflow to +0; row max can't advance).
// Q/K/V read directly from permuted g_C column blocks (row stride 6144B).
// Smem 55.3KB -> 2 CTAs/SM.
// ---------------------------------------------------------------------------
#define ASTR 72
#define AQT  (128 * ASTR)                     // Q tile halfs (9216)
#define AKT  (64 * ASTR)                      // K/V tile halfs (4608)
#define AQ_OFF 0
#define AK_OFF(b)  (AQT + (b) * AKT)
#define AV_OFF(b)  (AQT + 2 * AKT + (b) * AKT)
#define ATTN_SMEM  ((AQT + 4 * AKT) * 2)      // 55296 bytes

__global__ __launch_bounds__(256, 2) void attn_kernel()
{
    extern __shared__ __half asm_[];
    uint32_t sb = smem_u32(asm_);
    __half* Qs = asm_ + AQ_OFF;

    int tid  = threadIdx.x;
    int bh   = blockIdx.y;
    int qt   = blockIdx.x;
    int q0   = qt * 128;
    int warp = tid >> 5, lane = tid & 31;
    int g    = lane >> 2, tg = lane & 3;
    int lrow = lane & 15;
    int lcol = (lane >> 4) * 8;

    int bi = bh >> 4;
    int h  = bh & 15;

    int r0 = warp * 16 + g;                // 0..127
    int r1 = r0 + 8;
    int qg0 = q0 + r0, qg1 = q0 + r1;

    // per-(b,h) base pointers into the permuted QKV buffer
    const __half* Cb = g_C + (size_t)bi * NS * N_QKV + h * NDH;
    const __half* Qg = Cb;                 // t = 0 (pre-scaled by 1/8)
    const __half* Kg = Cb + ND;            // t = 1
    const __half* Vg = Cb + 2 * ND;        // t = 2

    int ntiles = 2 * qt + 2;               // 64-row KV tiles covering [0, q0+128)

    auto prefetch = [&](int kt, int b) {
        const __half* Ksrc = Kg + (size_t)(kt * 64) * N_QKV;
        const __half* Vsrc = Vg + (size_t)(kt * 64) * N_QKV;
        uint32_t kdst = sb + AK_OFF(b) * 2;
        uint32_t vdst = sb + AV_OFF(b) * 2;
        #pragma unroll
        for (int i = 0; i < 2; i++) {
            int ch  = tid + i * 256;           // 0..511
            int row = ch >> 3, q = ch & 7;
            uint32_t doff = (uint32_t)(row * ASTR + q * 8) * 2u;
            cp16(kdst + doff, Ksrc + (size_t)row * N_QKV + q * 8);
            cp16(vdst + doff, Vsrc + (size_t)row * N_QKV + q * 8);
        }
        cp_commit();
    };

    prefetch(0, 0);

    // load Q tile: 128 rows x 8 chunks = 1024 chunks over 256 threads
    #pragma unroll
    for (int it = 0; it < 4; it++) {
        int ch  = tid + it * 256;
        int row = ch >> 3, q = ch & 7;
        *(uint4*)&Qs[row * ASTR + q * 8] =
            *(const uint4*)(Qg + (size_t)(q0 + row) * N_QKV + q * 8);
    }
    __syncthreads();               // Q tile visible to ldmatrix

    // hoisted Q fragments (invariant across all KV tiles)
    unsigned qf[4][4];
    #pragma unroll
    for (int kk = 0; kk < 4; kk++)
        ldm4(qf[kk][0], qf[kk][1], qf[kk][2], qf[kk][3],
             sb + (uint32_t)((warp * 16 + lrow) * ASTR + kk * 16 + lcol) * 2u);

    float o[8][4];
    #pragma unroll
    for (int j = 0; j < 8; j++)
        #pragma unroll
        for (int e = 0; e < 4; e++) o[j][e] = 0.f;
    float m_run0 = -1e30f, m_run1 = -1e30f;
    float l_run0 = 0.f,    l_run1 = 0.f;

    const unsigned ONES = 0x3C003C00u;        // half2(1.0, 1.0)

    for (int kt = 0; kt < ntiles; kt++) {
        int buf = kt & 1;
        if (kt + 1 < ntiles) prefetch(kt + 1, buf ^ 1);
        if (kt + 1 < ntiles) cp_wait<1>(); else cp_wait<0>();
        __syncthreads();

        uint32_t Kb = sb + AK_OFF(buf) * 2;
        uint32_t Vb = sb + AV_OFF(buf) * 2;
        int k0 = kt * 64;

        // ---- S = Q @ K^T ----
        float sc[8][4];
        #pragma unroll
        for (int j = 0; j < 8; j++)
            #pragma unroll
            for (int e = 0; e < 4; e++) sc[j][e] = 0.f;
        #pragma unroll
        for (int kk = 0; kk < 4; kk++) {
            int kb = kk * 16;
            #pragma unroll
            for (int nt = 0; nt < 4; nt++) {
                unsigned r0q, r1q, r2q, r3q;
                ldm4(r0q, r1q, r2q, r3q,
                     Kb + (uint32_t)((nt * 16 + lrow) * ASTR + kb + lcol) * 2u);
                mma16(sc[nt * 2],     qf[kk][0], qf[kk][1], qf[kk][2], qf[kk][3], r0q, r2q);
                mma16(sc[nt * 2 + 1], qf[kk][0], qf[kk][1], qf[kk][2], qf[kk][3], r1q, r3q);
            }
        }

        // causal mask — only the last two KV tiles can clip any row
        if (kt >= 2 * qt) {
            #pragma unroll
            for (int j = 0; j < 8; j++)
                #pragma unroll
                for (int e = 0; e < 2; e++) {
                    int kv = k0 + j * 8 + 2 * tg + e;
                    if (kv > qg0) sc[j][e]     = -1e4f;
                    if (kv > qg1) sc[j][2 + e] = -1e4f;
                }
        }

        // ---- row max (fp32) ----
        float ml0 = -1e30f, ml1 = -1e30f;
        #pragma unroll
        for (int j = 0; j < 8; j++) {
            ml0 = fmaxf(ml0, fmaxf(sc[j][0], sc[j][1]));
            ml1 = fmaxf(ml1, fmaxf(sc[j][2], sc[j][3]));
        }
        ml0 = fmaxf(ml0, __shfl_xor_sync(0xffffffffu, ml0, 1));
        ml0 = fmaxf(ml0, __shfl_xor_sync(0xffffffffu, ml0, 2));
        ml1 = fmaxf(ml1, __shfl_xor_sync(0xffffffffu, ml1, 1));
        ml1 = fmaxf(ml1, __shfl_xor_sync(0xffffffffu, ml1, 2));
        float mn0 = fmaxf(m_run0, ml0);
        float mn1 = fmaxf(m_run1, ml1);

        // warp-vote: if no lane's max advanced, alpha == 1 exactly -> skip
        bool noresc = __all_sync(0xffffffffu,
                                 (mn0 == m_run0) && (mn1 == m_run1));
        if (!noresc) {
            float al0 = __expf(m_run0 - mn0);
            float al1 = __expf(m_run1 - mn1);
            l_run0 *= al0;
            l_run1 *= al1;
            #pragma unroll
            for (int j = 0; j < 8; j++) {
                o[j][0] *= al0;  o[j][1] *= al0;
                o[j][2] *= al1;  o[j][3] *= al1;
            }
            m_run0 = mn0;
            m_run1 = mn1;
        }
        float mnl0 = mn0 * LOG2E;
        float mnl1 = mn1 * LOG2E;

        // ---- p = 2^((s-mn)*log2e) in fp16 pairs; these are the PV A-frags ----
        unsigned pr0[8], pr1[8];
        #pragma unroll
        for (int j = 0; j < 8; j++) {
            float t0 = fmaf(sc[j][0], LOG2E, -mnl0);
            float t1 = fmaf(sc[j][1], LOG2E, -mnl0);
            float t2 = fmaf(sc[j][2], LOG2E, -mnl1);
            float t3 = fmaf(sc[j][3], LOG2E, -mnl1);
            pr0[j] = ex2_h2(pack_h2(t0, t1));
            pr1[j] = ex2_h2(pack_h2(t2, t3));
        }

        // ---- l-tile via ones-mma (exact fp32 row sums of p) ----
        float lacc[4] = {0.f, 0.f, 0.f, 0.f};
        #pragma unroll
        for (int u = 0; u < 4; u++)
            mma16(lacc, pr0[2 * u], pr1[2 * u], pr0[2 * u + 1], pr1[2 * u + 1],
                  ONES, ONES);
        l_run0 += lacc[0];
        l_run1 += lacc[2];

        // ---- O += P @ V  (A-frags from registers; V via trans ldmatrix) ----
        #pragma unroll
        for (int u = 0; u < 4; u++) {
            int kb = u * 16;
            unsigned a0 = pr0[2 * u],     a1 = pr1[2 * u];
            unsigned a2 = pr0[2 * u + 1], a3 = pr1[2 * u + 1];
            #pragma unroll
            for (int nt = 0; nt < 4; nt++) {
                unsigned r0q, r1q, r2q, r3q;
                ldm4t(r0q, r1q, r2q, r3q,
                      Vb + (uint32_t)((kb + lrow) * ASTR + nt * 16 + lcol) * 2u);
                mma16(o[nt * 2],     a0, a1, a2, a3, r0q, r1q);
                mma16(o[nt * 2 + 1], a0, a1, a2, a3, r2q, r3q);
            }
        }
        __syncthreads();   // K/V reads done before next prefetch overwrites
    }

    float inv0 = 1.f / l_run0;
    float inv1 = 1.f / l_run1;
    __half* d0 = g_ctx + ((size_t)(bi * NS) + qg0) * ND + h * NDH;
    __half* d1 = g_ctx + ((size_t)(bi * NS) + qg1) * ND + h * NDH;
    #pragma unroll
    for (int j = 0; j < 8; j++) {
        int cc = j * 8 + 2 * tg;
        *(__half2*)(d0 + cc) = __floats2half2_rn(o[j][0] * inv0, o[j][1] * inv0);
        *(__half2*)(d1 + cc) = __floats2half2_rn(o[j][2] * inv1, o[j][3] * inv1);
    }
}

// ---------------------------------------------------------------------------
// Launch (graph-capturable, allocation-free).
// Inputs: query, mask(unused — causal is static), W_qkv, b_qkv, W_out, b_out.
// ---------------------------------------------------------------------------
extern "C" void kernel_launch(void* const* d_in, const int* in_sizes, int n_in,
                              void* d_out, int out_size)
{
    const float* query = (const float*)d_in[0];
    const float* W_qkv = (const float*)d_in[2];
    const float* b_qkv = (const float*)d_in[3];
    const float* W_out = (const float*)d_in[4];
    const float* b_out = (const float*)d_in[5];
    float* out = (float*)d_out;

    cudaFuncSetAttribute(attn_kernel,
                         cudaFuncAttributeMaxDynamicSharedMemorySize, ATTN_SMEM);
    cudaFuncSetAttribute(mm_gemm_kernel<0>,
                         cudaFuncAttributeMaxDynamicSharedMemorySize, GEMM_SMEM);
    cudaFuncSetAttribute(mm_gemm_kernel<1>,
                         cudaFuncAttributeMaxDynamicSharedMemorySize, GEMM_SMEM);

    __half* Ah;      cudaGetSymbolAddress((void**)&Ah, g_Ah);
    __half* Wt_qkv;  cudaGetSymbolAddress((void**)&Wt_qkv, g_Wt_qkv);
    __half* Wt_out;  cudaGetSymbolAddress((void**)&Wt_out, g_Wt_out);
    __half* ctx;     cudaGetSymbolAddress((void**)&ctx, g_ctx);
    float*  bq;      cudaGetSymbolAddress((void**)&bq, g_bq);

    // Prepasses: convert A; permuted+scaled transpose of W_qkv/bias; W_out.
    round_h_kernel<<<(size_t)NM * ND / 1024, 256>>>(query, Ah);
    transpose_perm_qkv_kernel<<<dim3(N_QKV / 32, ND / 32), 256>>>(W_qkv, Wt_qkv);
    bias_perm_kernel<<<N_QKV / 256, 256>>>(b_qkv);
    transpose_h_kernel<<<dim3(ND / 32, ND / 32), 256>>>(W_out, Wt_out, ND, ND);

    // QKV projection -> g_C in native [t][h][dh] column layout
    mm_gemm_kernel<0><<<dim3(N_QKV / 128, NM / 128), 256, GEMM_SMEM>>>(
        Ah, Wt_qkv, bq, nullptr);

    // Attention  (128-row q tiles) — reads g_C slices directly
    attn_kernel<<<dim3(NS / 128, NBH), 256, ATTN_SMEM>>>();

    // Output projection
    mm_gemm_kernel<1><<<dim3(ND / 128, NM / 128), 256, GEMM_SMEM>>>(
        ctx, Wt_out, b_out, out);
}

// round 16
// speedup vs baseline: 1.0276x; 1.0276x over previous
#include <cuda_runtime.h>
#include <cuda_fp16.h>
#include <cstdint>

// Problem dims
#define NB   4
#define NS   2048
#define ND   1024
#define NH   16
#define NDH  64
#define NBH  (NB * NH)     // 64
#define NM   (NB * NS)     // 8192 tokens
#define N_QKV (3 * ND)     // 3072
#define LOG2E 1.4426950408889634f

// Scratch (static __device__ arrays: allocation-free per harness rules)
// g_C layout: [m][n'] with n' = t*1024 + h*64 + dh  (t: 0=q,1=k,2=v)
__device__ __align__(16) __half g_C[(size_t)NM * N_QKV];
__device__ __half g_ctx[(size_t)NM * ND];          // [b][s][d]
__device__ __half g_Ah[(size_t)NM * ND];           // query, fp16
__device__ __half g_Wt_qkv[(size_t)N_QKV * ND];    // permuted W_qkv^T [3072][1024]
__device__ __half g_Wt_out[(size_t)ND * ND];       // W_out^T [1024][1024]
__device__ float  g_bq[N_QKV];                     // permuted (+Q-scaled) bias

// ---------------------------------------------------------------------------
// helpers
// ---------------------------------------------------------------------------
__device__ __forceinline__ uint32_t smem_u32(const void* p) {
    uint32_t a;
    asm("{ .reg .u64 t; cvta.to.shared.u64 t, %1; cvt.u32.u64 %0, t; }"
        : "=r"(a) : "l"(p));
    return a;
}
__device__ __forceinline__ void cp16(uint32_t dst, const void* src) {
    asm volatile("cp.async.cg.shared.global [%0], [%1], 16;"
                 :: "r"(dst), "l"(src) : "memory");
}
__device__ __forceinline__ void cp_commit() {
    asm volatile("cp.async.commit_group;" ::: "memory");
}
template <int N>
__device__ __forceinline__ void cp_wait() {
    asm volatile("cp.async.wait_group %0;" :: "n"(N) : "memory");
}

// fp16 m16n8k16 mma, fp32 accumulate
__device__ __forceinline__ void mma16(float* c,
                                      unsigned a0, unsigned a1, unsigned a2, unsigned a3,
                                      unsigned b0, unsigned b1) {
    asm volatile(
        "mma.sync.aligned.m16n8k16.row.col.f32.f16.f16.f32 "
        "{%0,%1,%2,%3},{%4,%5,%6,%7},{%8,%9},{%0,%1,%2,%3};"
        : "+f"(c[0]), "+f"(c[1]), "+f"(c[2]), "+f"(c[3])
        : "r"(a0), "r"(a1), "r"(a2), "r"(a3), "r"(b0), "r"(b1));
}

__device__ __forceinline__ void ldm4(unsigned& r0, unsigned& r1, unsigned& r2,
                                     unsigned& r3, uint32_t addr) {
    asm volatile("ldmatrix.sync.aligned.m8n8.x4.shared.b16 {%0,%1,%2,%3}, [%4];"
                 : "=r"(r0), "=r"(r1), "=r"(r2), "=r"(r3) : "r"(addr));
}
__device__ __forceinline__ void ldm4t(unsigned& r0, unsigned& r1, unsigned& r2,
                                      unsigned& r3, uint32_t addr) {
    asm volatile("ldmatrix.sync.aligned.m8n8.x4.trans.shared.b16 {%0,%1,%2,%3}, [%4];"
                 : "=r"(r0), "=r"(r1), "=r"(r2), "=r"(r3) : "r"(addr));
}

// pack two fp32 -> half2 {lo=a, hi=b}
__device__ __forceinline__ unsigned pack_h2(float lo, float hi) {
    unsigned d;
    asm("cvt.rn.f16x2.f32 %0, %1, %2;" : "=r"(d) : "f"(hi), "f"(lo));
    return d;
}
// 2^x for both halves of a half2
__device__ __forceinline__ unsigned ex2_h2(unsigned x) {
    unsigned d;
    asm("ex2.approx.f16x2 %0, %1;" : "=r"(d) : "r"(x));
    return d;
}

// ---------------------------------------------------------------------------
// Prepass: fp32 -> fp16 (4 elements/thread)
// ---------------------------------------------------------------------------
__global__ __launch_bounds__(256) void round_h_kernel(
    const float* __restrict__ src, __half* __restrict__ dst)
{
    size_t i = ((size_t)blockIdx.x * 256 + threadIdx.x) * 4;
    float4 v = *(const float4*)(src + i);
    *(__half2*)(dst + i)     = __floats2half2_rn(v.x, v.y);
    *(__half2*)(dst + i + 2) = __floats2half2_rn(v.z, v.w);
}

// ---------------------------------------------------------------------------
// Transpose + fp16 convert:  dst[C][R] = h(src[R][C])   (W_out path)
// ---------------------------------------------------------------------------
__global__ __launch_bounds__(256) void transpose_h_kernel(
    const float* __restrict__ src, __half* __restrict__ dst, int R, int C)
{
    __shared__ float t[32][33];
    int bx = blockIdx.x * 32;
    int by = blockIdx.y * 32;
    int tx = threadIdx.x & 31, ty = threadIdx.x >> 5;
    #pragma unroll
    for (int j = 0; j < 4; j++)
        t[ty + j * 8][tx] = src[(size_t)(by + ty + j * 8) * C + bx + tx];
    __syncthreads();
    #pragma unroll
    for (int j = 0; j < 4; j++)
        dst[(size_t)(bx + ty + j * 8) * R + by + tx] =
            __float2half_rn(t[tx][ty + j * 8]);
}

// ---------------------------------------------------------------------------
// Permuted transpose of W_qkv:  dst[n'][k] = h(W[k][n] * s),
// n' = t*1024 + h*64 + dh,  n = h*192 + dh*3 + t,  s = (t==0 ? 0.125 : 1).
// ---------------------------------------------------------------------------
__global__ __launch_bounds__(256) void transpose_perm_qkv_kernel(
    const float* __restrict__ W, __half* __restrict__ dst)
{
    __shared__ float t[32][33];
    int npb = blockIdx.x * 32;
    int kb  = blockIdx.y * 32;
    int tx = threadIdx.x & 31, ty = threadIdx.x >> 5;

    int tt  = npb >> 10;
    int rem = npb & 1023;
    int h   = rem >> 6;
    int dh0 = rem & 63;
    int nbase = h * 192 + dh0 * 3 + tt;
    float scale = (tt == 0) ? 0.125f : 1.0f;

    #pragma unroll
    for (int j = 0; j < 4; j++)
        t[tx][ty + j * 8] = W[(size_t)(kb + ty + j * 8) * N_QKV + nbase + tx * 3];
    __syncthreads();
    #pragma unroll
    for (int j = 0; j < 4; j++)
        dst[(size_t)(npb + ty + j * 8) * ND + kb + tx] =
            __float2half_rn(t[ty + j * 8][tx] * scale);
}

// permuted (+Q-scaled) bias: g_bq[n'] = b[n] * s
__global__ __launch_bounds__(256) void bias_perm_kernel(const float* __restrict__ b)
{
    int np = blockIdx.x * 256 + threadIdx.x;     // 0..3071
    int tt = np >> 10;
    int rem = np & 1023;
    int h = rem >> 6, dh = rem & 63;
    int n = h * 192 + dh * 3 + tt;
    g_bq[np] = b[n] * ((tt == 0) ? 0.125f : 1.0f);
}

// ---------------------------------------------------------------------------
// fp16 mma GEMM (round-10 mainloop — best measured; byte-identical).
// Block tile 128x128, BK=64, 3-stage cp.async pipeline, ONE sync/stage,
// 8 warps in 2x4, warp tile 64x32.  110.6KB smem -> 2 CTAs/SM.
// MODE 0: coalesced half2 C(+bias) stores to g_C (permuted layout).
// MODE 1: fp32 out = acc + bias.
// ---------------------------------------------------------------------------
#define GS    72                          // smem row stride (halfs)
#define GT    (128 * GS)                  // halfs per tile (9216)
#define GSTG  (2 * GT)                    // halfs per stage A+B (18432)
#define GEMM_SMEM (3 * GSTG * 2)          // 110592 bytes
#define NSTAGE_K 16                       // K=1024 / BK=64

template <int MODE>
__global__ __launch_bounds__(256, 2) void mm_gemm_kernel(
    const __half* __restrict__ A,
    const __half* __restrict__ Bt,
    const float* __restrict__ bias,
    float* __restrict__ outp)
{
    extern __shared__ __half hsm[];
    uint32_t sb = smem_u32(hsm);

    int tid  = threadIdx.x;
    int warp = tid >> 5, lane = tid & 31;
    int wm   = warp >> 2, wn = warp & 3;      // 2 x 4 warp grid, tile 64x32
    int g    = lane >> 2, tg = lane & 3;
    int m0   = blockIdx.y * 128;
    int n0   = blockIdx.x * 128;

    int lrow = lane & 15;
    int lcol = (lane >> 4) * 8;

    float acc[4][4][4];
    #pragma unroll
    for (int i = 0; i < 4; i++)
        #pragma unroll
        for (int j = 0; j < 4; j++)
            #pragma unroll
            for (int e = 0; e < 4; e++) acc[i][j][e] = 0.f;

    auto prefetch = [&](int t) {
        int st = t % 3;
        int k0 = t * 64;
        uint32_t abase = sb + (uint32_t)(st * GSTG) * 2u;
        uint32_t bbase = abase + (uint32_t)GT * 2u;
        #pragma unroll
        for (int i = 0; i < 4; i++) {
            int ch  = tid + i * 256;              // 0..1023
            int row = ch >> 3, q = ch & 7;
            uint32_t doff = (uint32_t)(row * GS + q * 8) * 2u;
            cp16(abase + doff, A  + (size_t)(m0 + row) * 1024 + k0 + q * 8);
            cp16(bbase + doff, Bt + (size_t)(n0 + row) * 1024 + k0 + q * 8);
        }
        cp_commit();
    };

    prefetch(0);
    prefetch(1);

    for (int s = 0; s < NSTAGE_K; s++) {
        if (s < NSTAGE_K - 1) cp_wait<1>(); else cp_wait<0>();
        __syncthreads();
        if (s + 2 < NSTAGE_K) prefetch(s + 2);

        uint32_t Ab = sb + (uint32_t)((s % 3) * GSTG) * 2u;
        uint32_t Bb = Ab + (uint32_t)GT * 2u;
        #pragma unroll
        for (int kk = 0; kk < 4; kk++) {
            int kb = kk * 16;
            unsigned af[4][4], bf[4][2];
            #pragma unroll
            for (int i = 0; i < 4; i++) {
                uint32_t addr = Ab + (uint32_t)((wm * 64 + i * 16 + lrow) * GS + kb + lcol) * 2u;
                ldm4(af[i][0], af[i][1], af[i][2], af[i][3], addr);
            }
            #pragma unroll
            for (int nt = 0; nt < 2; nt++) {
                unsigned r0, r1, r2, r3;
                uint32_t addr = Bb + (uint32_t)((wn * 32 + nt * 16 + lrow) * GS + kb + lcol) * 2u;
                ldm4(r0, r1, r2, r3, addr);
                bf[nt * 2][0] = r0;  bf[nt * 2 + 1][0] = r1;
                bf[nt * 2][1] = r2;  bf[nt * 2 + 1][1] = r3;
            }
            #pragma unroll
            for (int i = 0; i < 4; i++)
                #pragma unroll
                for (int j = 0; j < 4; j++)
                    mma16(acc[i][j], af[i][0], af[i][1], af[i][2], af[i][3],
                          bf[j][0], bf[j][1]);
        }
    }

    if (MODE == 0) {
        #pragma unroll
        for (int i = 0; i < 4; i++)
            #pragma unroll
            for (int half = 0; half < 2; half++) {
                int m = m0 + wm * 64 + i * 16 + g + half * 8;
                #pragma unroll
                for (int j = 0; j < 4; j++) {
                    int n = n0 + wn * 32 + j * 8 + 2 * tg;
                    __half2 hv = __floats2half2_rn(
                        acc[i][j][half * 2 + 0] + bias[n],
                        acc[i][j][half * 2 + 1] + bias[n + 1]);
                    *(__half2*)(g_C + (size_t)m * N_QKV + n) = hv;
                }
            }
    } else {
        #pragma unroll
        for (int i = 0; i < 4; i++)
            #pragma unroll
            for (int half = 0; half < 2; half++) {
                int m = m0 + wm * 64 + i * 16 + g + half * 8;
                #pragma unroll
                for (int j = 0; j < 4; j++) {
                    int n = n0 + wn * 32 + j * 8 + 2 * tg;
                    float2 v = make_float2(acc[i][j][half * 2 + 0] + bias[n],
                                           acc[i][j][half * 2 + 1] + bias[n + 1]);
                    *(float2*)(outp + (size_t)m * ND + n) = v;
                }
            }
    }
}

// ---------------------------------------------------------------------------
// Causal flash attention (round-14 version, byte-identical math).
// ONE change: qt = 31 - blockIdx.x, so the heaviest (largest-qt) CTAs launch
// first and the light ones pack the tail wave (triangular-work scheduling).
// Q/K/V read directly from permuted g_C column blocks (row stride 6144B).
// ---------------------------------------------------------------------------
#define ASTR 72
#define AT   (64 * ASTR)
#define AQ_OFF 0
#define AK_OFF(b)  (AT + (b) * AT)
#define AV_OFF(b)  (3 * AT + (b) * AT)
#define ATTN_SMEM  (5 * AT * 2)               // 46080 bytes

__global__ __launch_bounds__(128) void attn_kernel()
{
    extern __shared__ __half asm_[];
    uint32_t sb = smem_u32(asm_);
    __half* Qs = asm_ + AQ_OFF;

    int tid  = threadIdx.x;
    int bh   = blockIdx.y;
    int qt   = (int)gridDim.x - 1 - (int)blockIdx.x;   // heavy tiles first
    int q0   = qt * 64;
    int warp = tid >> 5, lane = tid & 31;
    int g    = lane >> 2, tg = lane & 3;
    int lrow = lane & 15;
    int lcol = (lane >> 4) * 8;

    int bi = bh >> 4;
    int h  = bh & 15;

    int r0 = warp * 16 + g;
    int r1 = r0 + 8;
    int qg0 = q0 + r0, qg1 = q0 + r1;

    // per-(b,h) base pointers into the permuted QKV buffer
    const __half* Cb = g_C + (size_t)bi * NS * N_QKV + h * NDH;
    const __half* Qg = Cb;                 // t = 0 (pre-scaled by 1/8)
    const __half* Kg = Cb + ND;            // t = 1
    const __half* Vg = Cb + 2 * ND;        // t = 2

    auto prefetch = [&](int kt, int b) {
        const __half* Ksrc = Kg + (size_t)(kt * 64) * N_QKV;
        const __half* Vsrc = Vg + (size_t)(kt * 64) * N_QKV;
        uint32_t kdst = sb + AK_OFF(b) * 2;
        uint32_t vdst = sb + AV_OFF(b) * 2;
        #pragma unroll
        for (int i = 0; i < 4; i++) {
            int ch  = tid + i * 128;
            int row = ch >> 3, q = ch & 7;
            uint32_t doff = (uint32_t)(row * ASTR + q * 8) * 2u;
            cp16(kdst + doff, Ksrc + (size_t)row * N_QKV + q * 8);
            cp16(vdst + doff, Vsrc + (size_t)row * N_QKV + q * 8);
        }
        cp_commit();
    };

    prefetch(0, 0);

    #pragma unroll
    for (int it = 0; it < 4; it++) {
        int ch  = tid + it * 128;
        int row = ch >> 3, q = ch & 7;
        *(uint4*)&Qs[row * ASTR + q * 8] =
            *(const uint4*)(Qg + (size_t)(q0 + row) * N_QKV + q * 8);
    }
    __syncthreads();               // Q tile visible to ldmatrix

    // hoisted Q fragments (invariant across all KV tiles)
    unsigned qf[4][4];
    #pragma unroll
    for (int kk = 0; kk < 4; kk++)
        ldm4(qf[kk][0], qf[kk][1], qf[kk][2], qf[kk][3],
             sb + (uint32_t)((warp * 16 + lrow) * ASTR + kk * 16 + lcol) * 2u);

    float o[8][4];
    #pragma unroll
    for (int j = 0; j < 8; j++)
        #pragma unroll
        for (int e = 0; e < 4; e++) o[j][e] = 0.f;
    float m_run0 = -1e30f, m_run1 = -1e30f;
    float l_run0 = 0.f,    l_run1 = 0.f;

    const unsigned ONES = 0x3C003C00u;        // half2(1.0, 1.0)

    for (int kt = 0; kt <= qt; kt++) {
        int buf = kt & 1;
        if (kt < qt) prefetch(kt + 1, buf ^ 1);
        if (kt < qt) cp_wait<1>(); else cp_wait<0>();
        __syncthreads();

        uint32_t Kb = sb + AK_OFF(buf) * 2;
        uint32_t Vb = sb + AV_OFF(buf) * 2;
        int k0 = kt * 64;

        // ---- S = Q @ K^T ----
        float sc[8][4];
        #pragma unroll
        for (int j = 0; j < 8; j++)
            #pragma unroll
            for (int e = 0; e < 4; e++) sc[j][e] = 0.f;
        #pragma unroll
        for (int kk = 0; kk < 4; kk++) {
            int kb = kk * 16;
            #pragma unroll
            for (int nt = 0; nt < 4; nt++) {
                unsigned r0q, r1q, r2q, r3q;
                ldm4(r0q, r1q, r2q, r3q,
                     Kb + (uint32_t)((nt * 16 + lrow) * ASTR + kb + lcol) * 2u);
                mma16(sc[nt * 2],     qf[kk][0], qf[kk][1], qf[kk][2], qf[kk][3], r0q, r2q);
                mma16(sc[nt * 2 + 1], qf[kk][0], qf[kk][1], qf[kk][2], qf[kk][3], r1q, r3q);
            }
        }

        // causal mask (diagonal tile only); -1e4 keeps t fp16-representable
        if (kt == qt) {
            #pragma unroll
            for (int j = 0; j < 8; j++)
                #pragma unroll
                for (int e = 0; e < 2; e++) {
                    int kv = k0 + j * 8 + 2 * tg + e;
                    if (kv > qg0) sc[j][e]     = -1e4f;
                    if (kv > qg1) sc[j][2 + e] = -1e4f;
                }
        }

        // ---- row max (fp32) ----
        float ml0 = -1e30f, ml1 = -1e30f;
        #pragma unroll
        for (int j = 0; j < 8; j++) {
            ml0 = fmaxf(ml0, fmaxf(sc[j][0], sc[j][1]));
            ml1 = fmaxf(ml1, fmaxf(sc[j][2], sc[j][3]));
        }
        ml0 = fmaxf(ml0, __shfl_xor_sync(0xffffffffu, ml0, 1));
        ml0 = fmaxf(ml0, __shfl_xor_sync(0xffffffffu, ml0, 2));
        ml1 = fmaxf(ml1, __shfl_xor_sync(0xffffffffu, ml1, 1));
        ml1 = fmaxf(ml1, __shfl_xor_sync(0xffffffffu, ml1, 2));
        float mn0 = fmaxf(m_run0, ml0);
        float mn1 = fmaxf(m_run1, ml1);

        // warp-vote: if no lane's max advanced, alpha == 1 exactly -> skip
        bool noresc = __all_sync(0xffffffffu,
                                 (mn0 == m_run0) && (mn1 == m_run1));
        if (!noresc) {
            float al0 = __expf(m_run0 - mn0);
            float al1 = __expf(m_run1 - mn1);
            l_run0 *= al0;
            l_run1 *= al1;
            #pragma unroll
            for (int j = 0; j < 8; j++) {
                o[j][0] *= al0;  o[j][1] *= al0;
                o[j][2] *= al1;  o[j][3] *= al1;
            }
            m_run0 = mn0;
            m_run1 = mn1;
        }
        float mnl0 = mn0 * LOG2E;
        float mnl1 = mn1 * LOG2E;

        // ---- p = 2^((s-mn)*log2e) in fp16 pairs; these are the PV A-frags ----
        unsigned pr0[8], pr1[8];
        #pragma unroll
        for (int j = 0; j < 8; j++) {
            float t0 = fmaf(sc[j][0], LOG2E, -mnl0);
            float t1 = fmaf(sc[j][1], LOG2E, -mnl0);
            float t2 = fmaf(sc[j][2], LOG2E, -mnl1);
            float t3 = fmaf(sc[j][3], LOG2E, -mnl1);
            pr0[j] = ex2_h2(pack_h2(t0, t1));
            pr1[j] = ex2_h2(pack_h2(t2, t3));
        }

        // ---- l-tile via ones-mma (exact fp32 row sums of p) ----
        float lacc[4] = {0.f, 0.f, 0.f, 0.f};
        #pragma unroll
        for (int u = 0; u < 4; u++)
            mma16(lacc, pr0[2 * u], pr1[2 * u], pr0[2 * u + 1], pr1[2 * u + 1],
                  ONES, ONES);
        l_run0 += lacc[0];
        l_run1 += lacc[2];

        // ---- O += P @ V  (A-frags from registers; V via trans ldmatrix) ----
        #pragma unroll
        for (int u = 0; u < 4; u++) {
            int kb = u * 16;
            unsigned a0 = pr0[2 * u],     a1 = pr1[2 * u];
            unsigned a2 = pr0[2 * u + 1], a3 = pr1[2 * u + 1];
            #pragma unroll
            for (int nt = 0; nt < 4; nt++) {
                unsigned r0q, r1q, r2q, r3q;
                ldm4t(r0q, r1q, r2q, r3q,
                      Vb + (uint32_t)((kb + lrow) * ASTR + nt * 16 + lcol) * 2u);
                mma16(o[nt * 2],     a0, a1, a2, a3, r0q, r1q);
                mma16(o[nt * 2 + 1], a0, a1, a2, a3, r2q, r3q);
            }
        }
        __syncthreads();   // K/V reads done before next prefetch overwrites
    }

    float inv0 = 1.f / l_run0;
    float inv1 = 1.f / l_run1;
    __half* d0 = g_ctx + ((size_t)(bi * NS) + qg0) * ND + h * NDH;
    __half* d1 = g_ctx + ((size_t)(bi * NS) + qg1) * ND + h * NDH;
    #pragma unroll
    for (int j = 0; j < 8; j++) {
        int cc = j * 8 + 2 * tg;
        *(__half2*)(d0 + cc) = __floats2half2_rn(o[j][0] * inv0, o[j][1] * inv0);
        *(__half2*)(d1 + cc) = __floats2half2_rn(o[j][2] * inv1, o[j][3] * inv1);
    }
}

// ---------------------------------------------------------------------------
// Launch (graph-capturable, allocation-free).
// Inputs: query, mask(unused — causal is static), W_qkv, b_qkv, W_out, b_out.
// ---------------------------------------------------------------------------
extern "C" void kernel_launch(void* const* d_in, const int* in_sizes, int n_in,
                              void* d_out, int out_size)
{
    const float* query = (const float*)d_in[0];
    const float* W_qkv = (const float*)d_in[2];
    const float* b_qkv = (const float*)d_in[3];
    const float* W_out = (const float*)d_in[4];
    const float* b_out = (const float*)d_in[5];
    float* out = (float*)d_out;

    cudaFuncSetAttribute(attn_kernel,
                         cudaFuncAttributeMaxDynamicSharedMemorySize, ATTN_SMEM);
    cudaFuncSetAttribute(mm_gemm_kernel<0>,
                         cudaFuncAttributeMaxDynamicSharedMemorySize, GEMM_SMEM);
    cudaFuncSetAttribute(mm_gemm_kernel<1>,
                         cudaFuncAttributeMaxDynamicSharedMemorySize, GEMM_SMEM);

    __half* Ah;      cudaGetSymbolAddress((void**)&Ah, g_Ah);
    __half* Wt_qkv;  cudaGetSymbolAddress((void**)&Wt_qkv, g_Wt_qkv);
    __half* Wt_out;  cudaGetSymbolAddress((void**)&Wt_out, g_Wt_out);
    __half* ctx;     cudaGetSymbolAddress((void**)&ctx, g_ctx);
    float*  bq;      cudaGetSymbolAddress((void**)&bq, g_bq);

    // Prepasses: convert A; permuted+scaled transpose of W_qkv/bias; W_out.
    round_h_kernel<<<(size_t)NM * ND / 1024, 256>>>(query, Ah);
    transpose_perm_qkv_kernel<<<dim3(N_QKV / 32, ND / 32), 256>>>(W_qkv, Wt_qkv);
    bias_perm_kernel<<<N_QKV / 256, 256>>>(b_qkv);
    transpose_h_kernel<<<dim3(ND / 32, ND / 32), 256>>>(W_out, Wt_out, ND, ND);

    // QKV projection -> g_C in native [t][h][dh] column layout
    mm_gemm_kernel<0><<<dim3(N_QKV / 128, NM / 128), 256, GEMM_SMEM>>>(
        Ah, Wt_qkv, bq, nullptr);

    // Attention  (64-row q tiles, heavy-first scheduling)
    attn_kernel<<<dim3(NS / 64, NBH), 128, ATTN_SMEM>>>();

    // Output projection
    mm_gemm_kernel<1><<<dim3(ND / 128, NM / 128), 256, GEMM_SMEM>>>(
        ctx, Wt_out, b_out, out);
}